// round 2
// baseline (speedup 1.0000x reference)
#include <cuda_runtime.h>
#include <cstdint>

#define NN   50000
#define EE   640000
#define HIDD 128

// ---------------- device scratch (no allocations allowed) ----------------
__device__ float g_k[NN * HIDD];        // k projections, later reused as MLP ping buffer
__device__ float g_q[NN * HIDD];        // q projections, later reused as MLP pong buffer
__device__ float g_ft[NN * HIDD];       // scatter accumulator, later he2
__device__ float g_z[EE * 8];           // edge logits, then exp(z - zmax)
__device__ float g_zmax[NN * 8];
__device__ float g_denom[NN * 8];
__device__ float g_Wt[8][HIDD * HIDD];  // transposed weights: Wt[in][o]

// ---------------- weight transpose: Wt[in][o] = W[o][in] ----------------
__global__ void transpose_w(const float* w0, const float* w1, const float* w2, const float* w3,
                            const float* w4, const float* w5, const float* w6, const float* w7)
{
    __shared__ float tile[32][33];
    const float* W;
    switch (blockIdx.z) {
        case 0: W = w0; break; case 1: W = w1; break;
        case 2: W = w2; break; case 3: W = w3; break;
        case 4: W = w4; break; case 5: W = w5; break;
        case 6: W = w6; break; default: W = w7; break;
    }
    float* Out = g_Wt[blockIdx.z];
    int x0 = blockIdx.x * 32;   // in
    int y0 = blockIdx.y * 32;   // o
    int tx = threadIdx.x;
    for (int j = threadIdx.y; j < 32; j += 8)
        tile[j][tx] = W[(y0 + j) * HIDD + x0 + tx];
    __syncthreads();
    for (int j = threadIdx.y; j < 32; j += 8)
        Out[(x0 + j) * HIDD + y0 + tx] = tile[tx][j];
}

// ---------------- init ft=0, zmax=-inf, denom=0 ----------------
__global__ void init_bufs()
{
    int i = blockIdx.x * blockDim.x + threadIdx.x;
    if (i < NN * HIDD) g_ft[i] = 0.f;
    if (i < NN * 8) {
        g_zmax[i]  = __int_as_float(0xff800000);  // -inf
        g_denom[i] = 0.f;
    }
}

// ---------------- generic 128-wide GEMM: Y = act(X @ W^T + b) [+ res] ----------------
// Wt is pre-transposed: Wt[in*128 + o].
// Tile: 64 rows x 128 cols, 256 threads, thread = (co 0..31 cols*4, ro 0..7 rows*8).
__global__ __launch_bounds__(256) void gemm128(
    const float* __restrict__ X, const float* __restrict__ Wt,
    const float* __restrict__ bias, const float* __restrict__ res,
    float* __restrict__ Y, int n, int doRelu)
{
    __shared__ float Ws[64][HIDD];  // 32 KB : Ws[in_local][o]
    __shared__ float Xs[64][64];    // 16 KB : Xs[row][in_local]

    int tid = threadIdx.x;
    int co  = tid & 31;   // column group: cols 4*co .. 4*co+3 (lane id -> conflict-free f4)
    int ro  = tid >> 5;   // row group: rows 8*ro .. 8*ro+7 (warp-uniform -> broadcast x)
    int row0 = blockIdx.x * 64;

    float acc[8][4];
#pragma unroll
    for (int r = 0; r < 8; r++)
#pragma unroll
        for (int j = 0; j < 4; j++) acc[r][j] = 0.f;

    for (int k0 = 0; k0 < HIDD; k0 += 64) {
        if (k0) __syncthreads();
        // load 64 rows of Wt (rows k0..k0+63), coalesced, conflict-free
        for (int i = tid; i < 64 * 32; i += 256) {
            int il = i >> 5, g = i & 31;
            ((float4*)Ws[il])[g] = ((const float4*)(Wt + (size_t)(k0 + il) * HIDD))[g];
        }
        // load X tile [64 rows x 64 in]
        for (int i = tid; i < 64 * 16; i += 256) {
            int r = i >> 4, g = i & 15;
            int grow = row0 + r;
            float4 v = make_float4(0.f, 0.f, 0.f, 0.f);
            if (grow < n) v = ((const float4*)(X + (size_t)grow * HIDD + k0))[g];
            ((float4*)Xs[r])[g] = v;
        }
        __syncthreads();

#pragma unroll
        for (int i4 = 0; i4 < 16; i4++) {
            float4 xv[8];
#pragma unroll
            for (int r = 0; r < 8; r++) xv[r] = ((float4*)Xs[ro * 8 + r])[i4];  // broadcast
#pragma unroll
            for (int j = 0; j < 4; j++) {
                float4 wv = ((float4*)Ws[i4 * 4 + j])[co];                       // conflict-free
#pragma unroll
                for (int r = 0; r < 8; r++) {
                    float x = (j == 0) ? xv[r].x : (j == 1) ? xv[r].y : (j == 2) ? xv[r].z : xv[r].w;
                    acc[r][0] += x * wv.x;
                    acc[r][1] += x * wv.y;
                    acc[r][2] += x * wv.z;
                    acc[r][3] += x * wv.w;
                }
            }
        }
    }

    float4 b = ((const float4*)bias)[co];
#pragma unroll
    for (int r = 0; r < 8; r++) {
        int grow = row0 + ro * 8 + r;
        if (grow >= n) continue;
        float4 o;
        o.x = acc[r][0] + b.x; o.y = acc[r][1] + b.y;
        o.z = acc[r][2] + b.z; o.w = acc[r][3] + b.w;
        if (doRelu) {
            o.x = fmaxf(o.x, 0.f); o.y = fmaxf(o.y, 0.f);
            o.z = fmaxf(o.z, 0.f); o.w = fmaxf(o.w, 0.f);
        }
        if (res) {
            float4 rv = ((const float4*)(res + (size_t)grow * HIDD))[co];
            o.x += rv.x; o.y += rv.y; o.z += rv.z; o.w += rv.w;
        }
        ((float4*)(Y + (size_t)grow * HIDD))[co] = o;
    }
}

// ---------------- edge logits: z[e][h] = sum_d lrelu(k[src]+q[dst])*attn + dd[e]; segment max ----
__global__ void edge_logits(const int* __restrict__ src, const int* __restrict__ dst,
                            const float* __restrict__ attn, const float* __restrict__ dd,
                            int E)
{
    int e = blockIdx.x * 2 + (threadIdx.x >> 7);
    int t = threadIdx.x & 127;
    if (e >= E) return;
    int s = src[e], dn = dst[e];
    float v = g_k[(size_t)s * HIDD + t] + g_q[(size_t)dn * HIDD + t];
    v = (v > 0.f) ? v : 0.01f * v;                 // leaky relu, slope 0.01
    float p = v * attn[t];
#pragma unroll
    for (int o = 8; o; o >>= 1) p += __shfl_xor_sync(0xffffffffu, p, o, 16);
    if ((t & 15) == 0) {
        int h = t >> 4;
        float zz = p + dd[e];
        g_z[(size_t)e * 8 + h] = zz;
        float* addr = &g_zmax[dn * 8 + h];
        if (zz >= 0.f) atomicMax((int*)addr, __float_as_int(zz));
        else           atomicMin((unsigned int*)addr, (unsigned int)__float_as_int(zz));
    }
}

// ---------------- exp(z - zmax[dst]) in place + segment sum into denom ----------------
__global__ void edge_exp(const int* __restrict__ dst, int EH)
{
    int i = blockIdx.x * blockDim.x + threadIdx.x;
    if (i >= EH) return;
    int e = i >> 3, h = i & 7;
    int dn = dst[e];
    float ez = __expf(g_z[i] - g_zmax[dn * 8 + h]);
    g_z[i] = ez;
    atomicAdd(&g_denom[dn * 8 + h], ez);
}

// ---------------- scatter: ft[dst] += bond * ez/denom[dst] ----------------
__global__ void edge_scatter(const int* __restrict__ dst, const float* __restrict__ bond, int E)
{
    int e = blockIdx.x * 2 + (threadIdx.x >> 7);
    int t = threadIdx.x & 127;
    if (e >= E) return;
    int dn = dst[e];
    int h = t >> 4;
    float coef = g_z[(size_t)e * 8 + h] / g_denom[dn * 8 + h];
    atomicAdd(&g_ft[(size_t)dn * HIDD + t], bond[(size_t)e * HIDD + t] * coef);
}

// ---------------- launch ----------------
extern "C" void kernel_launch(void* const* d_in, const int* in_sizes, int n_in,
                              void* d_out, int out_size)
{
    const int*   src  = (const int*)d_in[0];
    const int*   dst  = (const int*)d_in[1];
    const float* bond = (const float*)d_in[2];
    const float* atom = (const float*)d_in[3];
    const float* dd   = (const float*)d_in[4];
    const float* k_w  = (const float*)d_in[5];
    const float* k_b  = (const float*)d_in[6];
    const float* q_w  = (const float*)d_in[7];
    const float* q_b  = (const float*)d_in[8];
    const float* attn = (const float*)d_in[9];
    const float* l1w  = (const float*)d_in[10];
    const float* l1b  = (const float*)d_in[11];
    const float* l2w  = (const float*)d_in[12];
    const float* l2b  = (const float*)d_in[13];
    const float* r1aw = (const float*)d_in[14];
    const float* r1ab = (const float*)d_in[15];
    const float* r1bw = (const float*)d_in[16];
    const float* r1bb = (const float*)d_in[17];
    const float* r2aw = (const float*)d_in[18];
    const float* r2ab = (const float*)d_in[19];
    const float* r2bw = (const float*)d_in[20];
    const float* r2bb = (const float*)d_in[21];
    float* out = (float*)d_out;

    int E = in_sizes[0];
    int n = in_sizes[3] / HIDD;

    float *kbuf, *qbuf, *ftbuf, *wt;
    cudaGetSymbolAddress((void**)&kbuf,  g_k);
    cudaGetSymbolAddress((void**)&qbuf,  g_q);
    cudaGetSymbolAddress((void**)&ftbuf, g_ft);
    cudaGetSymbolAddress((void**)&wt,    g_Wt);

    const float* WT[8];
    for (int i = 0; i < 8; i++) WT[i] = wt + (size_t)i * HIDD * HIDD;

    // 1. transpose all 8 weight matrices
    transpose_w<<<dim3(4, 4, 8), dim3(32, 8)>>>(k_w, q_w, l1w, l2w, r1aw, r1bw, r2aw, r2bw);

    // 2. init accumulators
    init_bufs<<<(n * HIDD + 255) / 256, 256>>>();

    int gblocks = (n + 63) / 64;
    // 3. k / q projections
    gemm128<<<gblocks, 256>>>(atom, WT[0], k_b, nullptr, kbuf, n, 0);
    gemm128<<<gblocks, 256>>>(atom, WT[1], q_b, nullptr, qbuf, n, 0);

    // 4. edge attention
    edge_logits<<<(E + 1) / 2, 256>>>(src, dst, attn, dd, E);
    edge_exp<<<(E * 8 + 255) / 256, 256>>>(dst, E * 8);
    edge_scatter<<<(E + 1) / 2, 256>>>(dst, bond, E);

    // 5. output MLP + residual chain
    // t1  = relu(lin1(ft))                 -> kbuf
    gemm128<<<gblocks, 256>>>(ftbuf, WT[2], l1b, nullptr, kbuf, n, 1);
    // he  = lin2(t1) + atom                -> qbuf
    gemm128<<<gblocks, 256>>>(kbuf, WT[3], l2b, atom, qbuf, n, 0);
    // u1  = relu(r1a(he))                  -> kbuf
    gemm128<<<gblocks, 256>>>(qbuf, WT[4], r1ab, nullptr, kbuf, n, 1);
    // he2 = relu(r1b(u1)) + he             -> ftbuf
    gemm128<<<gblocks, 256>>>(kbuf, WT[5], r1bb, qbuf, ftbuf, n, 1);
    // u3  = relu(r2a(he2))                 -> kbuf
    gemm128<<<gblocks, 256>>>(ftbuf, WT[6], r2ab, nullptr, kbuf, n, 1);
    // out = relu(r2b(u3)) + he2            -> d_out
    gemm128<<<gblocks, 256>>>(kbuf, WT[7], r2bb, ftbuf, out, n, 1);
}

// round 3
// speedup vs baseline: 1.8984x; 1.8984x over previous
#include <cuda_runtime.h>
#include <cstdint>

#define NN   50000
#define EE   640000
#define HIDD 128

// ---------------- device scratch (no allocations allowed) ----------------
__device__ float g_k[NN * HIDD];        // k projections, later reused as MLP ping buffer
__device__ float g_q[NN * HIDD];        // q projections, later reused as MLP pong buffer
__device__ float g_ft[NN * HIDD];       // aggregated messages, later he2
__device__ float g_Wt[8][HIDD * HIDD];  // transposed weights: Wt[in][o]
__device__ int   g_cnt[NN];             // in-degree histogram
__device__ int   g_off[NN + 1];         // CSR offsets
__device__ int   g_cur[NN];             // bucket cursors
__device__ int   g_eid[EE];             // edge ids grouped by dst
__device__ int   g_esrc[EE];            // src[e] grouped by dst (skip one indirection)

// ---------------- weight transpose: Wt[in][o] = W[o][in] ----------------
__global__ void transpose_w(const float* w0, const float* w1, const float* w2, const float* w3,
                            const float* w4, const float* w5, const float* w6, const float* w7)
{
    __shared__ float tile[32][33];
    const float* W;
    switch (blockIdx.z) {
        case 0: W = w0; break; case 1: W = w1; break;
        case 2: W = w2; break; case 3: W = w3; break;
        case 4: W = w4; break; case 5: W = w5; break;
        case 6: W = w6; break; default: W = w7; break;
    }
    float* Out = g_Wt[blockIdx.z];
    int x0 = blockIdx.x * 32;   // in
    int y0 = blockIdx.y * 32;   // o
    int tx = threadIdx.x;
    for (int j = threadIdx.y; j < 32; j += 8)
        tile[j][tx] = W[(y0 + j) * HIDD + x0 + tx];
    __syncthreads();
    for (int j = threadIdx.y; j < 32; j += 8)
        Out[(x0 + j) * HIDD + y0 + tx] = tile[tx][j];
}

// ---------------- CSR build ----------------
__global__ void zero_cnt(int n)
{
    int i = blockIdx.x * blockDim.x + threadIdx.x;
    if (i < n) g_cnt[i] = 0;
}

__global__ void count_deg(const int* __restrict__ dst, int E)
{
    int e = blockIdx.x * blockDim.x + threadIdx.x;
    if (e < E) atomicAdd(&g_cnt[dst[e]], 1);
}

// single-block exclusive scan of g_cnt[0..n) -> g_off / g_cur, g_off[n]=total
__global__ __launch_bounds__(1024) void scan_deg(int n)
{
    __shared__ int wsum[32];
    __shared__ int carry_s;
    __shared__ int btot;
    int tid  = threadIdx.x;
    int lane = tid & 31, wid = tid >> 5;
    if (tid == 0) carry_s = 0;
    __syncthreads();
    for (int base = 0; base < n; base += 1024) {
        int idx = base + tid;
        int v = (idx < n) ? g_cnt[idx] : 0;
        int incl = v;
#pragma unroll
        for (int o = 1; o < 32; o <<= 1) {
            int t = __shfl_up_sync(0xffffffffu, incl, o);
            if (lane >= o) incl += t;
        }
        if (lane == 31) wsum[wid] = incl;
        __syncthreads();
        if (wid == 0) {
            int wv = wsum[lane];
            int winc = wv;
#pragma unroll
            for (int o = 1; o < 32; o <<= 1) {
                int t = __shfl_up_sync(0xffffffffu, winc, o);
                if (lane >= o) winc += t;
            }
            if (lane == 31) btot = winc;
            wsum[lane] = winc - wv;   // exclusive warp offsets
        }
        __syncthreads();
        int excl = carry_s + wsum[wid] + incl - v;
        if (idx < n) { g_off[idx] = excl; g_cur[idx] = excl; }
        __syncthreads();
        if (tid == 0) carry_s += btot;
        __syncthreads();
    }
    if (threadIdx.x == 0) g_off[n] = carry_s;
}

__global__ void bucket_edges(const int* __restrict__ src, const int* __restrict__ dst, int E)
{
    int e = blockIdx.x * blockDim.x + threadIdx.x;
    if (e >= E) return;
    int p = atomicAdd(&g_cur[dst[e]], 1);
    g_eid[p]  = e;
    g_esrc[p] = src[e];
}

// ---------------- fused per-node online-softmax aggregation ----------------
// one block (128 thr) per dst node; thread t owns feature t, head h = t>>4.
__global__ __launch_bounds__(128) void node_aggregate(
    const float* __restrict__ bond, const float* __restrict__ dd,
    const float* __restrict__ attn)
{
    int node = blockIdx.x;
    int t = threadIdx.x;
    int beg = g_off[node], end = g_off[node + 1];

    float qv = g_q[(size_t)node * HIDD + t];
    float av = attn[t];

    float m = __int_as_float(0xff800000);  // -inf
    float s = 0.f, acc = 0.f;

    float kv = 0.f, bv = 0.f, ddv = 0.f;
    if (beg < end) {
        int e = g_eid[beg], sn = g_esrc[beg];
        kv  = g_k[(size_t)sn * HIDD + t];
        bv  = bond[(size_t)e * HIDD + t];
        ddv = dd[e];
    }

    for (int i = beg; i < end; i++) {
        // prefetch next edge while we do this edge's reduction chain
        float kv2 = 0.f, bv2 = 0.f, ddv2 = 0.f;
        if (i + 1 < end) {
            int e2 = g_eid[i + 1], s2 = g_esrc[i + 1];
            kv2  = g_k[(size_t)s2 * HIDD + t];
            bv2  = bond[(size_t)e2 * HIDD + t];
            ddv2 = dd[e2];
        }
        float v = kv + qv;
        v = (v > 0.f) ? v : 0.01f * v;            // leaky relu
        float p = v * av;
#pragma unroll
        for (int o = 8; o; o >>= 1) p += __shfl_xor_sync(0xffffffffu, p, o, 16);
        float z = p + ddv;                         // all 16 lanes of the head group hold z
        float mn   = fmaxf(m, z);
        float corr = __expf(m - mn);               // first iter: exp(-inf)=0
        float w    = __expf(z - mn);
        acc = acc * corr + w * bv;
        s   = s   * corr + w;
        m   = mn;
        kv = kv2; bv = bv2; ddv = ddv2;
    }
    g_ft[(size_t)node * HIDD + t] = (s > 0.f) ? acc / s : 0.f;
}

// ---------------- generic 128-wide GEMM: Y = act(X @ W^T + b) [+ res] ----------------
__global__ __launch_bounds__(256) void gemm128(
    const float* __restrict__ X, const float* __restrict__ Wt,
    const float* __restrict__ bias, const float* __restrict__ res,
    float* __restrict__ Y, int n, int doRelu)
{
    __shared__ float Ws[64][HIDD];  // 32 KB : Ws[in_local][o]
    __shared__ float Xs[64][64];    // 16 KB : Xs[row][in_local]

    int tid = threadIdx.x;
    int co  = tid & 31;
    int ro  = tid >> 5;
    int row0 = blockIdx.x * 64;

    float acc[8][4];
#pragma unroll
    for (int r = 0; r < 8; r++)
#pragma unroll
        for (int j = 0; j < 4; j++) acc[r][j] = 0.f;

    for (int k0 = 0; k0 < HIDD; k0 += 64) {
        if (k0) __syncthreads();
        for (int i = tid; i < 64 * 32; i += 256) {
            int il = i >> 5, g = i & 31;
            ((float4*)Ws[il])[g] = ((const float4*)(Wt + (size_t)(k0 + il) * HIDD))[g];
        }
        for (int i = tid; i < 64 * 16; i += 256) {
            int r = i >> 4, g = i & 15;
            int grow = row0 + r;
            float4 v = make_float4(0.f, 0.f, 0.f, 0.f);
            if (grow < n) v = ((const float4*)(X + (size_t)grow * HIDD + k0))[g];
            ((float4*)Xs[r])[g] = v;
        }
        __syncthreads();

#pragma unroll
        for (int i4 = 0; i4 < 16; i4++) {
            float4 xv[8];
#pragma unroll
            for (int r = 0; r < 8; r++) xv[r] = ((float4*)Xs[ro * 8 + r])[i4];
#pragma unroll
            for (int j = 0; j < 4; j++) {
                float4 wv = ((float4*)Ws[i4 * 4 + j])[co];
#pragma unroll
                for (int r = 0; r < 8; r++) {
                    float x = (j == 0) ? xv[r].x : (j == 1) ? xv[r].y : (j == 2) ? xv[r].z : xv[r].w;
                    acc[r][0] += x * wv.x;
                    acc[r][1] += x * wv.y;
                    acc[r][2] += x * wv.z;
                    acc[r][3] += x * wv.w;
                }
            }
        }
    }

    float4 b = ((const float4*)bias)[co];
#pragma unroll
    for (int r = 0; r < 8; r++) {
        int grow = row0 + ro * 8 + r;
        if (grow >= n) continue;
        float4 o;
        o.x = acc[r][0] + b.x; o.y = acc[r][1] + b.y;
        o.z = acc[r][2] + b.z; o.w = acc[r][3] + b.w;
        if (doRelu) {
            o.x = fmaxf(o.x, 0.f); o.y = fmaxf(o.y, 0.f);
            o.z = fmaxf(o.z, 0.f); o.w = fmaxf(o.w, 0.f);
        }
        if (res) {
            float4 rv = ((const float4*)(res + (size_t)grow * HIDD))[co];
            o.x += rv.x; o.y += rv.y; o.z += rv.z; o.w += rv.w;
        }
        ((float4*)(Y + (size_t)grow * HIDD))[co] = o;
    }
}

// ---------------- launch ----------------
extern "C" void kernel_launch(void* const* d_in, const int* in_sizes, int n_in,
                              void* d_out, int out_size)
{
    const int*   src  = (const int*)d_in[0];
    const int*   dst  = (const int*)d_in[1];
    const float* bond = (const float*)d_in[2];
    const float* atom = (const float*)d_in[3];
    const float* dd   = (const float*)d_in[4];
    const float* k_w  = (const float*)d_in[5];
    const float* k_b  = (const float*)d_in[6];
    const float* q_w  = (const float*)d_in[7];
    const float* q_b  = (const float*)d_in[8];
    const float* attn = (const float*)d_in[9];
    const float* l1w  = (const float*)d_in[10];
    const float* l1b  = (const float*)d_in[11];
    const float* l2w  = (const float*)d_in[12];
    const float* l2b  = (const float*)d_in[13];
    const float* r1aw = (const float*)d_in[14];
    const float* r1ab = (const float*)d_in[15];
    const float* r1bw = (const float*)d_in[16];
    const float* r1bb = (const float*)d_in[17];
    const float* r2aw = (const float*)d_in[18];
    const float* r2ab = (const float*)d_in[19];
    const float* r2bw = (const float*)d_in[20];
    const float* r2bb = (const float*)d_in[21];
    float* out = (float*)d_out;

    int E = in_sizes[0];
    int n = in_sizes[3] / HIDD;

    float *kbuf, *qbuf, *ftbuf, *wt;
    cudaGetSymbolAddress((void**)&kbuf,  g_k);
    cudaGetSymbolAddress((void**)&qbuf,  g_q);
    cudaGetSymbolAddress((void**)&ftbuf, g_ft);
    cudaGetSymbolAddress((void**)&wt,    g_Wt);

    const float* WT[8];
    for (int i = 0; i < 8; i++) WT[i] = wt + (size_t)i * HIDD * HIDD;

    // weights + CSR build
    transpose_w<<<dim3(4, 4, 8), dim3(32, 8)>>>(k_w, q_w, l1w, l2w, r1aw, r1bw, r2aw, r2bw);
    zero_cnt<<<(n + 255) / 256, 256>>>(n);
    count_deg<<<(E + 255) / 256, 256>>>(dst, E);
    scan_deg<<<1, 1024>>>(n);
    bucket_edges<<<(E + 255) / 256, 256>>>(src, dst, E);

    int gblocks = (n + 63) / 64;
    // k / q projections
    gemm128<<<gblocks, 256>>>(atom, WT[0], k_b, nullptr, kbuf, n, 0);
    gemm128<<<gblocks, 256>>>(atom, WT[1], q_b, nullptr, qbuf, n, 0);

    // fused edge softmax + message aggregation (no float atomics)
    node_aggregate<<<n, 128>>>(bond, dd, attn);

    // output MLP + residual chain
    gemm128<<<gblocks, 256>>>(ftbuf, WT[2], l1b, nullptr, kbuf, n, 1);   // t1
    gemm128<<<gblocks, 256>>>(kbuf, WT[3], l2b, atom, qbuf, n, 0);       // he
    gemm128<<<gblocks, 256>>>(qbuf, WT[4], r1ab, nullptr, kbuf, n, 1);   // u1
    gemm128<<<gblocks, 256>>>(kbuf, WT[5], r1bb, qbuf, ftbuf, n, 1);     // he2
    gemm128<<<gblocks, 256>>>(ftbuf, WT[6], r2ab, nullptr, kbuf, n, 1);  // u3
    gemm128<<<gblocks, 256>>>(kbuf, WT[7], r2bb, ftbuf, out, n, 1);      // out
}

// round 4
// speedup vs baseline: 2.1302x; 1.1221x over previous
#include <cuda_runtime.h>
#include <cstdint>

#define NN   50000
#define EE   640000
#define HIDD 128

// ---------------- device scratch ----------------
__device__ float g_k[NN * HIDD];
__device__ float g_q[NN * HIDD];
__device__ float g_ft[NN * HIDD];
__device__ float g_Wt[8][HIDD * HIDD];
__device__ int   g_cnt[NN];
__device__ int   g_off[NN + 1];
__device__ int   g_cur[NN];
__device__ int   g_eid[EE];
__device__ int   g_esrc[EE];
__device__ int   g_bsum[256];
__device__ int   g_boff[256];

// ---------------- f32x2 helpers ----------------
__device__ __forceinline__ unsigned long long ffma2(unsigned long long a, unsigned long long b,
                                                    unsigned long long c)
{
    unsigned long long d;
    asm("fma.rn.f32x2 %0, %1, %2, %3;" : "=l"(d) : "l"(a), "l"(b), "l"(c));
    return d;
}
__device__ __forceinline__ unsigned long long splat2(float x)
{
    unsigned long long d;
    asm("mov.b64 %0, {%1, %1};" : "=l"(d) : "f"(x));
    return d;
}
__device__ __forceinline__ float2 unpack2(unsigned long long a)
{
    float2 v;
    asm("mov.b64 {%0, %1}, %2;" : "=f"(v.x), "=f"(v.y) : "l"(a));
    return v;
}
__device__ __forceinline__ unsigned long long pack2(float x, float y)
{
    unsigned long long d;
    asm("mov.b64 %0, {%1, %2};" : "=l"(d) : "f"(x), "f"(y));
    return d;
}

// ---------------- weight transpose: Wt[in][o] = W[o][in] ----------------
__global__ void transpose_w(const float* w0, const float* w1, const float* w2, const float* w3,
                            const float* w4, const float* w5, const float* w6, const float* w7)
{
    __shared__ float tile[32][33];
    const float* W;
    switch (blockIdx.z) {
        case 0: W = w0; break; case 1: W = w1; break;
        case 2: W = w2; break; case 3: W = w3; break;
        case 4: W = w4; break; case 5: W = w5; break;
        case 6: W = w6; break; default: W = w7; break;
    }
    float* Out = g_Wt[blockIdx.z];
    int x0 = blockIdx.x * 32;
    int y0 = blockIdx.y * 32;
    int tx = threadIdx.x;
    for (int j = threadIdx.y; j < 32; j += 8)
        tile[j][tx] = W[(y0 + j) * HIDD + x0 + tx];
    __syncthreads();
    for (int j = threadIdx.y; j < 32; j += 8)
        Out[(x0 + j) * HIDD + y0 + tx] = tile[tx][j];
}

// ---------------- CSR build ----------------
__global__ void zero_cnt(int n)
{
    int i = blockIdx.x * blockDim.x + threadIdx.x;
    if (i < n) g_cnt[i] = 0;
}

__global__ void count_deg(const int* __restrict__ dst, int E)
{
    int e = blockIdx.x * blockDim.x + threadIdx.x;
    if (e < E) atomicAdd(&g_cnt[dst[e]], 1);
}

// hierarchical scan, stage 1: per-block exclusive scan + block sums
__global__ __launch_bounds__(256) void scan_blk(int n)
{
    __shared__ int ws[8];
    int b = blockIdx.x, t = threadIdx.x;
    int idx = b * 256 + t;
    int lane = t & 31, wid = t >> 5;
    int v = (idx < n) ? g_cnt[idx] : 0;
    int incl = v;
#pragma unroll
    for (int o = 1; o < 32; o <<= 1) {
        int u = __shfl_up_sync(0xffffffffu, incl, o);
        if (lane >= o) incl += u;
    }
    if (lane == 31) ws[wid] = incl;
    __syncthreads();
    if (t < 8) {
        int a = ws[t];
        int p = a;
#pragma unroll
        for (int o = 1; o < 8; o <<= 1) {
            int u = __shfl_up_sync(0xffu, p, o);
            if (t >= o) p += u;
        }
        ws[t] = p - a;
        if (t == 7) g_bsum[b] = p;
    }
    __syncthreads();
    if (idx < n) g_off[idx] = incl - v + ws[wid];
}

// stage 2: scan of block sums (nb <= 256) in one block
__global__ __launch_bounds__(256) void scan_tot(int nb, int n)
{
    __shared__ int ws[8];
    int t = threadIdx.x;
    int lane = t & 31, wid = t >> 5;
    int v = (t < nb) ? g_bsum[t] : 0;
    int incl = v;
#pragma unroll
    for (int o = 1; o < 32; o <<= 1) {
        int u = __shfl_up_sync(0xffffffffu, incl, o);
        if (lane >= o) incl += u;
    }
    if (lane == 31) ws[wid] = incl;
    __syncthreads();
    if (t < 8) {
        int a = ws[t];
        int p = a;
#pragma unroll
        for (int o = 1; o < 8; o <<= 1) {
            int u = __shfl_up_sync(0xffu, p, o);
            if (t >= o) p += u;
        }
        ws[t] = p - a;
        if (t == 7) g_off[n] = p;   // total = E
    }
    __syncthreads();
    g_boff[t] = incl - v + ws[wid];
}

// stage 3: add block offsets
__global__ void scan_add(int n)
{
    int b = blockIdx.x, t = threadIdx.x;
    int idx = b * 256 + t;
    if (idx < n) {
        int o = g_off[idx] + g_boff[b];
        g_off[idx] = o;
        g_cur[idx] = o;
    }
}

__global__ void bucket_edges(const int* __restrict__ src, const int* __restrict__ dst, int E)
{
    int e = blockIdx.x * blockDim.x + threadIdx.x;
    if (e >= E) return;
    int p = atomicAdd(&g_cur[dst[e]], 1);
    g_eid[p]  = e;
    g_esrc[p] = src[e];
}

// ---------------- fused per-node online-softmax aggregation ----------------
__global__ __launch_bounds__(128) void node_aggregate(
    const float* __restrict__ bond, const float* __restrict__ dd,
    const float* __restrict__ attn)
{
    int node = blockIdx.x;
    int t = threadIdx.x;
    int beg = g_off[node], end = g_off[node + 1];

    float qv = g_q[(size_t)node * HIDD + t];
    float av = attn[t];

    float m = __int_as_float(0xff800000);
    float s = 0.f, acc = 0.f;

    float kv = 0.f, bv = 0.f, ddv = 0.f;
    if (beg < end) {
        int e = g_eid[beg], sn = g_esrc[beg];
        kv  = g_k[(size_t)sn * HIDD + t];
        bv  = bond[(size_t)e * HIDD + t];
        ddv = dd[e];
    }

    for (int i = beg; i < end; i++) {
        float kv2 = 0.f, bv2 = 0.f, ddv2 = 0.f;
        if (i + 1 < end) {
            int e2 = g_eid[i + 1], s2 = g_esrc[i + 1];
            kv2  = g_k[(size_t)s2 * HIDD + t];
            bv2  = bond[(size_t)e2 * HIDD + t];
            ddv2 = dd[e2];
        }
        float v = kv + qv;
        v = (v > 0.f) ? v : 0.01f * v;
        float p = v * av;
#pragma unroll
        for (int o = 8; o; o >>= 1) p += __shfl_xor_sync(0xffffffffu, p, o, 16);
        float z = p + ddv;
        float mn   = fmaxf(m, z);
        float corr = __expf(m - mn);
        float w    = __expf(z - mn);
        acc = acc * corr + w * bv;
        s   = s   * corr + w;
        m   = mn;
        kv = kv2; bv = bv2; ddv = ddv2;
    }
    g_ft[(size_t)node * HIDD + t] = (s > 0.f) ? acc / s : 0.f;
}

// ---------------- f32x2 GEMM: Y = act(X @ W^T + b) [+ res] ----------------
// Tile 64 rows x 128 cols, 256 threads. Thread: rows r0..r0+3 (r0 = (tid>>4)*4),
// cols c0..c0+3 and c0+64..c0+67 (c0 = (tid&15)*4). Accumulators are f32x2 pairs.
#define KC 32
#define XPITCH 36
__global__ __launch_bounds__(256, 3) void gemm_f2(
    const float* __restrict__ X, const float* __restrict__ Wt,
    const float* __restrict__ bias, const float* __restrict__ res,
    float* __restrict__ Y, int n, int doRelu)
{
    __shared__ float Ws[KC][HIDD];       // 16 KB  Ws[k][col]
    __shared__ float Xs[64][XPITCH];     // 9 KB   Xs[row][k]

    int tid = threadIdx.x;
    int cg  = tid & 15;
    int rg  = tid >> 4;
    int c0  = cg * 4;
    int r0  = rg * 4;
    int row0 = blockIdx.x * 64;

    unsigned long long acc[4][4];
#pragma unroll
    for (int r = 0; r < 4; r++)
#pragma unroll
        for (int j = 0; j < 4; j++) acc[r][j] = 0ull;

    for (int k0 = 0; k0 < HIDD; k0 += KC) {
        if (k0) __syncthreads();
        // Ws: 32x128 floats = 1024 float4, 4 per thread, coalesced
#pragma unroll
        for (int j = 0; j < 4; j++) {
            int i = tid + 256 * j;
            int kk = i >> 5, cc = i & 31;
            ((float4*)Ws[kk])[cc] = ((const float4*)(Wt + (size_t)(k0 + kk) * HIDD))[cc];
        }
        // Xs: 64x32 floats = 512 float4, 2 per thread
#pragma unroll
        for (int j = 0; j < 2; j++) {
            int i = tid + 256 * j;
            int rr = i >> 3, f = i & 7;
            int grow = row0 + rr;
            float4 v = make_float4(0.f, 0.f, 0.f, 0.f);
            if (grow < n) v = ((const float4*)(X + (size_t)grow * HIDD + k0))[f];
            *(float4*)&Xs[rr][f * 4] = v;
        }
        __syncthreads();

#pragma unroll
        for (int k4 = 0; k4 < KC; k4 += 4) {
            float4 xf[4];
#pragma unroll
            for (int r = 0; r < 4; r++) xf[r] = *(const float4*)&Xs[r0 + r][k4];
#pragma unroll
            for (int kk = 0; kk < 4; kk++) {
                int k = k4 + kk;
                float4 wa = ((const float4*)Ws[k])[cg];
                float4 wb = ((const float4*)Ws[k])[cg + 16];
                unsigned long long w0 = pack2(wa.x, wa.y);
                unsigned long long w1 = pack2(wa.z, wa.w);
                unsigned long long w2 = pack2(wb.x, wb.y);
                unsigned long long w3 = pack2(wb.z, wb.w);
#pragma unroll
                for (int r = 0; r < 4; r++) {
                    float xs = (kk == 0) ? xf[r].x : (kk == 1) ? xf[r].y
                             : (kk == 2) ? xf[r].z : xf[r].w;
                    unsigned long long x2 = splat2(xs);
                    acc[r][0] = ffma2(x2, w0, acc[r][0]);
                    acc[r][1] = ffma2(x2, w1, acc[r][1]);
                    acc[r][2] = ffma2(x2, w2, acc[r][2]);
                    acc[r][3] = ffma2(x2, w3, acc[r][3]);
                }
            }
        }
    }

    float4 ba = ((const float4*)bias)[cg];
    float4 bb = ((const float4*)bias)[cg + 16];
#pragma unroll
    for (int r = 0; r < 4; r++) {
        int grow = row0 + r0 + r;
        if (grow >= n) continue;
        float2 a0 = unpack2(acc[r][0]);
        float2 a1 = unpack2(acc[r][1]);
        float2 a2 = unpack2(acc[r][2]);
        float2 a3 = unpack2(acc[r][3]);
        float4 oa = make_float4(a0.x + ba.x, a0.y + ba.y, a1.x + ba.z, a1.y + ba.w);
        float4 ob = make_float4(a2.x + bb.x, a2.y + bb.y, a3.x + bb.z, a3.y + bb.w);
        if (doRelu) {
            oa.x = fmaxf(oa.x, 0.f); oa.y = fmaxf(oa.y, 0.f);
            oa.z = fmaxf(oa.z, 0.f); oa.w = fmaxf(oa.w, 0.f);
            ob.x = fmaxf(ob.x, 0.f); ob.y = fmaxf(ob.y, 0.f);
            ob.z = fmaxf(ob.z, 0.f); ob.w = fmaxf(ob.w, 0.f);
        }
        if (res) {
            float4 ra = ((const float4*)(res + (size_t)grow * HIDD))[cg];
            float4 rb = ((const float4*)(res + (size_t)grow * HIDD))[cg + 16];
            oa.x += ra.x; oa.y += ra.y; oa.z += ra.z; oa.w += ra.w;
            ob.x += rb.x; ob.y += rb.y; ob.z += rb.z; ob.w += rb.w;
        }
        ((float4*)(Y + (size_t)grow * HIDD))[cg]      = oa;
        ((float4*)(Y + (size_t)grow * HIDD))[cg + 16] = ob;
    }
}

// ---------------- launch ----------------
extern "C" void kernel_launch(void* const* d_in, const int* in_sizes, int n_in,
                              void* d_out, int out_size)
{
    const int*   src  = (const int*)d_in[0];
    const int*   dst  = (const int*)d_in[1];
    const float* bond = (const float*)d_in[2];
    const float* atom = (const float*)d_in[3];
    const float* dd   = (const float*)d_in[4];
    const float* k_w  = (const float*)d_in[5];
    const float* k_b  = (const float*)d_in[6];
    const float* q_w  = (const float*)d_in[7];
    const float* q_b  = (const float*)d_in[8];
    const float* attn = (const float*)d_in[9];
    const float* l1w  = (const float*)d_in[10];
    const float* l1b  = (const float*)d_in[11];
    const float* l2w  = (const float*)d_in[12];
    const float* l2b  = (const float*)d_in[13];
    const float* r1aw = (const float*)d_in[14];
    const float* r1ab = (const float*)d_in[15];
    const float* r1bw = (const float*)d_in[16];
    const float* r1bb = (const float*)d_in[17];
    const float* r2aw = (const float*)d_in[18];
    const float* r2ab = (const float*)d_in[19];
    const float* r2bw = (const float*)d_in[20];
    const float* r2bb = (const float*)d_in[21];
    float* out = (float*)d_out;

    int E = in_sizes[0];
    int n = in_sizes[3] / HIDD;

    float *kbuf, *qbuf, *ftbuf, *wt;
    cudaGetSymbolAddress((void**)&kbuf,  g_k);
    cudaGetSymbolAddress((void**)&qbuf,  g_q);
    cudaGetSymbolAddress((void**)&ftbuf, g_ft);
    cudaGetSymbolAddress((void**)&wt,    g_Wt);

    const float* WT[8];
    for (int i = 0; i < 8; i++) WT[i] = wt + (size_t)i * HIDD * HIDD;

    int nb = (n + 255) / 256;   // 196 scan blocks

    // weights + CSR build
    transpose_w<<<dim3(4, 4, 8), dim3(32, 8)>>>(k_w, q_w, l1w, l2w, r1aw, r1bw, r2aw, r2bw);
    zero_cnt<<<nb, 256>>>(n);
    count_deg<<<(E + 255) / 256, 256>>>(dst, E);
    scan_blk<<<nb, 256>>>(n);
    scan_tot<<<1, 256>>>(nb, n);
    scan_add<<<nb, 256>>>(n);
    bucket_edges<<<(E + 255) / 256, 256>>>(src, dst, E);

    int gblocks = (n + 63) / 64;
    // k / q projections
    gemm_f2<<<gblocks, 256>>>(atom, WT[0], k_b, nullptr, kbuf, n, 0);
    gemm_f2<<<gblocks, 256>>>(atom, WT[1], q_b, nullptr, qbuf, n, 0);

    // fused edge softmax + message aggregation
    node_aggregate<<<n, 128>>>(bond, dd, attn);

    // output MLP + residual chain
    gemm_f2<<<gblocks, 256>>>(ftbuf, WT[2], l1b, nullptr, kbuf, n, 1);   // t1
    gemm_f2<<<gblocks, 256>>>(kbuf, WT[3], l2b, atom, qbuf, n, 0);       // he
    gemm_f2<<<gblocks, 256>>>(qbuf, WT[4], r1ab, nullptr, kbuf, n, 1);   // u1
    gemm_f2<<<gblocks, 256>>>(kbuf, WT[5], r1bb, qbuf, ftbuf, n, 1);     // he2
    gemm_f2<<<gblocks, 256>>>(ftbuf, WT[6], r2ab, nullptr, kbuf, n, 1);  // u3
    gemm_f2<<<gblocks, 256>>>(kbuf, WT[7], r2bb, ftbuf, out, n, 1);      // out
}

// round 5
// speedup vs baseline: 2.1939x; 1.0299x over previous
#include <cuda_runtime.h>
#include <cstdint>

#define NN   50000
#define EE   640000
#define HIDD 128

// ---------------- device scratch ----------------
__device__ float g_k[NN * HIDD];
__device__ float g_q[NN * HIDD];
__device__ float g_ft[NN * HIDD];
__device__ float g_Wt[8][HIDD * HIDD];
__device__ int   g_cnt[NN];
__device__ int   g_off[NN + 1];
__device__ int   g_cur[NN];
__device__ int   g_eid[EE];
__device__ int   g_esrc[EE];
__device__ int   g_bsum[256];
__device__ int   g_boff[256];

// ---------------- f32x2 helpers ----------------
__device__ __forceinline__ unsigned long long ffma2(unsigned long long a, unsigned long long b,
                                                    unsigned long long c)
{
    unsigned long long d;
    asm("fma.rn.f32x2 %0, %1, %2, %3;" : "=l"(d) : "l"(a), "l"(b), "l"(c));
    return d;
}
__device__ __forceinline__ unsigned long long splat2(float x)
{
    unsigned long long d;
    asm("mov.b64 %0, {%1, %1};" : "=l"(d) : "f"(x));
    return d;
}
__device__ __forceinline__ float2 unpack2(unsigned long long a)
{
    float2 v;
    asm("mov.b64 {%0, %1}, %2;" : "=f"(v.x), "=f"(v.y) : "l"(a));
    return v;
}
// packed pair load from shared: two u64 (four floats) with no packing movs
__device__ __forceinline__ void lds_v2b64(unsigned long long& a, unsigned long long& b,
                                          unsigned int saddr)
{
    asm volatile("ld.shared.v2.b64 {%0, %1}, [%2];" : "=l"(a), "=l"(b) : "r"(saddr));
}

// ---------------- weight transpose: Wt[in][o] = W[o][in] ----------------
__global__ void transpose_w(const float* w0, const float* w1, const float* w2, const float* w3,
                            const float* w4, const float* w5, const float* w6, const float* w7)
{
    __shared__ float tile[32][33];
    const float* W;
    switch (blockIdx.z) {
        case 0: W = w0; break; case 1: W = w1; break;
        case 2: W = w2; break; case 3: W = w3; break;
        case 4: W = w4; break; case 5: W = w5; break;
        case 6: W = w6; break; default: W = w7; break;
    }
    float* Out = g_Wt[blockIdx.z];
    int x0 = blockIdx.x * 32;
    int y0 = blockIdx.y * 32;
    int tx = threadIdx.x;
    for (int j = threadIdx.y; j < 32; j += 8)
        tile[j][tx] = W[(y0 + j) * HIDD + x0 + tx];
    __syncthreads();
    for (int j = threadIdx.y; j < 32; j += 8)
        Out[(x0 + j) * HIDD + y0 + tx] = tile[tx][j];
}

// ---------------- CSR build ----------------
__global__ void zero_cnt(int n)
{
    int i = blockIdx.x * blockDim.x + threadIdx.x;
    if (i < n) g_cnt[i] = 0;
}

__global__ void count_deg(const int* __restrict__ dst, int E)
{
    int e = blockIdx.x * blockDim.x + threadIdx.x;
    if (e < E) atomicAdd(&g_cnt[dst[e]], 1);
}

__global__ __launch_bounds__(256) void scan_blk(int n)
{
    __shared__ int ws[8];
    int b = blockIdx.x, t = threadIdx.x;
    int idx = b * 256 + t;
    int lane = t & 31, wid = t >> 5;
    int v = (idx < n) ? g_cnt[idx] : 0;
    int incl = v;
#pragma unroll
    for (int o = 1; o < 32; o <<= 1) {
        int u = __shfl_up_sync(0xffffffffu, incl, o);
        if (lane >= o) incl += u;
    }
    if (lane == 31) ws[wid] = incl;
    __syncthreads();
    if (t < 8) {
        int a = ws[t];
        int p = a;
#pragma unroll
        for (int o = 1; o < 8; o <<= 1) {
            int u = __shfl_up_sync(0xffu, p, o);
            if (t >= o) p += u;
        }
        ws[t] = p - a;
        if (t == 7) g_bsum[b] = p;
    }
    __syncthreads();
    if (idx < n) g_off[idx] = incl - v + ws[wid];
}

__global__ __launch_bounds__(256) void scan_tot(int nb, int n)
{
    __shared__ int ws[8];
    int t = threadIdx.x;
    int lane = t & 31, wid = t >> 5;
    int v = (t < nb) ? g_bsum[t] : 0;
    int incl = v;
#pragma unroll
    for (int o = 1; o < 32; o <<= 1) {
        int u = __shfl_up_sync(0xffffffffu, incl, o);
        if (lane >= o) incl += u;
    }
    if (lane == 31) ws[wid] = incl;
    __syncthreads();
    if (t < 8) {
        int a = ws[t];
        int p = a;
#pragma unroll
        for (int o = 1; o < 8; o <<= 1) {
            int u = __shfl_up_sync(0xffu, p, o);
            if (t >= o) p += u;
        }
        ws[t] = p - a;
        if (t == 7) g_off[n] = p;
    }
    __syncthreads();
    g_boff[t] = incl - v + ws[wid];
}

__global__ void scan_add(int n)
{
    int b = blockIdx.x, t = threadIdx.x;
    int idx = b * 256 + t;
    if (idx < n) {
        int o = g_off[idx] + g_boff[b];
        g_off[idx] = o;
        g_cur[idx] = o;
    }
}

__global__ void bucket_edges(const int* __restrict__ src, const int* __restrict__ dst, int E)
{
    int e = blockIdx.x * blockDim.x + threadIdx.x;
    if (e >= E) return;
    int p = atomicAdd(&g_cur[dst[e]], 1);
    g_eid[p]  = e;
    g_esrc[p] = src[e];
}

// ---------------- fused per-node online-softmax aggregation (2-edge unrolled) -------
__global__ __launch_bounds__(128) void node_aggregate(
    const float* __restrict__ bond, const float* __restrict__ dd,
    const float* __restrict__ attn)
{
    int node = blockIdx.x;
    int t = threadIdx.x;
    int beg = g_off[node], end = g_off[node + 1];

    float qv = g_q[(size_t)node * HIDD + t];
    float av = attn[t];

    float m = __int_as_float(0xff800000);
    float s = 0.f, acc = 0.f;

    int i = beg;
    for (; i + 1 < end; i += 2) {
        int e0 = g_eid[i],     s0 = g_esrc[i];
        int e1 = g_eid[i + 1], s1 = g_esrc[i + 1];
        float kv0 = g_k[(size_t)s0 * HIDD + t];
        float kv1 = g_k[(size_t)s1 * HIDD + t];
        float bv0 = bond[(size_t)e0 * HIDD + t];
        float bv1 = bond[(size_t)e1 * HIDD + t];
        float dd0 = dd[e0];
        float dd1 = dd[e1];

        float v0 = kv0 + qv; v0 = (v0 > 0.f) ? v0 : 0.01f * v0;
        float v1 = kv1 + qv; v1 = (v1 > 0.f) ? v1 : 0.01f * v1;
        float p0 = v0 * av;
        float p1 = v1 * av;
#pragma unroll
        for (int o = 8; o; o >>= 1) {
            p0 += __shfl_xor_sync(0xffffffffu, p0, o, 16);
            p1 += __shfl_xor_sync(0xffffffffu, p1, o, 16);
        }
        float z0 = p0 + dd0;
        float z1 = p1 + dd1;
        float mn = fmaxf(m, fmaxf(z0, z1));
        float corr = __expf(m - mn);
        float w0 = __expf(z0 - mn);
        float w1 = __expf(z1 - mn);
        acc = acc * corr + w0 * bv0 + w1 * bv1;
        s   = s   * corr + w0 + w1;
        m   = mn;
    }
    if (i < end) {
        int e0 = g_eid[i], s0 = g_esrc[i];
        float kv0 = g_k[(size_t)s0 * HIDD + t];
        float bv0 = bond[(size_t)e0 * HIDD + t];
        float dd0 = dd[e0];
        float v0 = kv0 + qv; v0 = (v0 > 0.f) ? v0 : 0.01f * v0;
        float p0 = v0 * av;
#pragma unroll
        for (int o = 8; o; o >>= 1) p0 += __shfl_xor_sync(0xffffffffu, p0, o, 16);
        float z0 = p0 + dd0;
        float mn = fmaxf(m, z0);
        float corr = __expf(m - mn);
        float w0 = __expf(z0 - mn);
        acc = acc * corr + w0 * bv0;
        s   = s   * corr + w0;
    }
    g_ft[(size_t)node * HIDD + t] = (s > 0.f) ? acc / s : 0.f;
}

// ---------------- f32x2 GEMM: Y = act(X @ W^T + b) [+ res] ----------------
// Tile 64 rows x 128 cols, 256 threads. Thread (cg 0..15, rg 0..15):
// rows rg*4..+3, cols cg*4..+3 and cg*4+64..+67. W pairs loaded via ld.shared.v2.b64.
#define KC 32
#define XPITCH 36
__global__ __launch_bounds__(256, 3) void gemm_f2(
    const float* __restrict__ X, const float* __restrict__ Wt,
    const float* __restrict__ bias, const float* __restrict__ res,
    float* __restrict__ Y, int n, int doRelu)
{
    __shared__ float Ws[KC][HIDD];       // 16 KB  Ws[k][col]
    __shared__ float Xs[64][XPITCH];     // 9 KB   Xs[row][k]

    int tid = threadIdx.x;
    int cg  = tid & 15;
    int rg  = tid >> 4;
    int r0  = rg * 4;
    int row0 = blockIdx.x * 64;

    // shared addresses for the W column pairs this thread reads
    unsigned int ws_base = (unsigned int)__cvta_generic_to_shared(&Ws[0][0]);
    unsigned int wA = ws_base + cg * 16;          // cols cg*4..+3
    unsigned int wB = wA + 256;                   // cols cg*4+64..+67

    unsigned long long acc[4][4];
#pragma unroll
    for (int r = 0; r < 4; r++)
#pragma unroll
        for (int j = 0; j < 4; j++) acc[r][j] = 0ull;

    for (int k0 = 0; k0 < HIDD; k0 += KC) {
        if (k0) __syncthreads();
#pragma unroll
        for (int j = 0; j < 4; j++) {
            int i = tid + 256 * j;
            int kk = i >> 5, cc = i & 31;
            ((float4*)Ws[kk])[cc] = ((const float4*)(Wt + (size_t)(k0 + kk) * HIDD))[cc];
        }
#pragma unroll
        for (int j = 0; j < 2; j++) {
            int i = tid + 256 * j;
            int rr = i >> 3, f = i & 7;
            int grow = row0 + rr;
            float4 v = make_float4(0.f, 0.f, 0.f, 0.f);
            if (grow < n) v = ((const float4*)(X + (size_t)grow * HIDD + k0))[f];
            *(float4*)&Xs[rr][f * 4] = v;
        }
        __syncthreads();

#pragma unroll
        for (int k4 = 0; k4 < KC; k4 += 4) {
            float4 xf[4];
#pragma unroll
            for (int r = 0; r < 4; r++) xf[r] = *(const float4*)&Xs[r0 + r][k4];
#pragma unroll
            for (int kk = 0; kk < 4; kk++) {
                int k = k4 + kk;
                unsigned long long w0, w1, w2, w3;
                lds_v2b64(w0, w1, wA + k * (HIDD * 4));
                lds_v2b64(w2, w3, wB + k * (HIDD * 4));
#pragma unroll
                for (int r = 0; r < 4; r++) {
                    float xs = (kk == 0) ? xf[r].x : (kk == 1) ? xf[r].y
                             : (kk == 2) ? xf[r].z : xf[r].w;
                    unsigned long long x2 = splat2(xs);
                    acc[r][0] = ffma2(x2, w0, acc[r][0]);
                    acc[r][1] = ffma2(x2, w1, acc[r][1]);
                    acc[r][2] = ffma2(x2, w2, acc[r][2]);
                    acc[r][3] = ffma2(x2, w3, acc[r][3]);
                }
            }
        }
    }

    float4 ba = ((const float4*)bias)[cg];
    float4 bb = ((const float4*)bias)[cg + 16];
#pragma unroll
    for (int r = 0; r < 4; r++) {
        int grow = row0 + r0 + r;
        if (grow >= n) continue;
        float2 a0 = unpack2(acc[r][0]);
        float2 a1 = unpack2(acc[r][1]);
        float2 a2 = unpack2(acc[r][2]);
        float2 a3 = unpack2(acc[r][3]);
        float4 oa = make_float4(a0.x + ba.x, a0.y + ba.y, a1.x + ba.z, a1.y + ba.w);
        float4 ob = make_float4(a2.x + bb.x, a2.y + bb.y, a3.x + bb.z, a3.y + bb.w);
        if (doRelu) {
            oa.x = fmaxf(oa.x, 0.f); oa.y = fmaxf(oa.y, 0.f);
            oa.z = fmaxf(oa.z, 0.f); oa.w = fmaxf(oa.w, 0.f);
            ob.x = fmaxf(ob.x, 0.f); ob.y = fmaxf(ob.y, 0.f);
            ob.z = fmaxf(ob.z, 0.f); ob.w = fmaxf(ob.w, 0.f);
        }
        if (res) {
            float4 ra = ((const float4*)(res + (size_t)grow * HIDD))[cg];
            float4 rb = ((const float4*)(res + (size_t)grow * HIDD))[cg + 16];
            oa.x += ra.x; oa.y += ra.y; oa.z += ra.z; oa.w += ra.w;
            ob.x += rb.x; ob.y += rb.y; ob.z += rb.z; ob.w += rb.w;
        }
        ((float4*)(Y + (size_t)grow * HIDD))[cg]      = oa;
        ((float4*)(Y + (size_t)grow * HIDD))[cg + 16] = ob;
    }
}

// ---------------- launch ----------------
extern "C" void kernel_launch(void* const* d_in, const int* in_sizes, int n_in,
                              void* d_out, int out_size)
{
    const int*   src  = (const int*)d_in[0];
    const int*   dst  = (const int*)d_in[1];
    const float* bond = (const float*)d_in[2];
    const float* atom = (const float*)d_in[3];
    const float* dd   = (const float*)d_in[4];
    const float* k_w  = (const float*)d_in[5];
    const float* k_b  = (const float*)d_in[6];
    const float* q_w  = (const float*)d_in[7];
    const float* q_b  = (const float*)d_in[8];
    const float* attn = (const float*)d_in[9];
    const float* l1w  = (const float*)d_in[10];
    const float* l1b  = (const float*)d_in[11];
    const float* l2w  = (const float*)d_in[12];
    const float* l2b  = (const float*)d_in[13];
    const float* r1aw = (const float*)d_in[14];
    const float* r1ab = (const float*)d_in[15];
    const float* r1bw = (const float*)d_in[16];
    const float* r1bb = (const float*)d_in[17];
    const float* r2aw = (const float*)d_in[18];
    const float* r2ab = (const float*)d_in[19];
    const float* r2bw = (const float*)d_in[20];
    const float* r2bb = (const float*)d_in[21];
    float* out = (float*)d_out;

    int E = in_sizes[0];
    int n = in_sizes[3] / HIDD;

    float *kbuf, *qbuf, *ftbuf, *wt;
    cudaGetSymbolAddress((void**)&kbuf,  g_k);
    cudaGetSymbolAddress((void**)&qbuf,  g_q);
    cudaGetSymbolAddress((void**)&ftbuf, g_ft);
    cudaGetSymbolAddress((void**)&wt,    g_Wt);

    const float* WT[8];
    for (int i = 0; i < 8; i++) WT[i] = wt + (size_t)i * HIDD * HIDD;

    int nb = (n + 255) / 256;

    transpose_w<<<dim3(4, 4, 8), dim3(32, 8)>>>(k_w, q_w, l1w, l2w, r1aw, r1bw, r2aw, r2bw);
    zero_cnt<<<nb, 256>>>(n);
    count_deg<<<(E + 255) / 256, 256>>>(dst, E);
    scan_blk<<<nb, 256>>>(n);
    scan_tot<<<1, 256>>>(nb, n);
    scan_add<<<nb, 256>>>(n);
    bucket_edges<<<(E + 255) / 256, 256>>>(src, dst, E);

    int gblocks = (n + 63) / 64;
    gemm_f2<<<gblocks, 256>>>(atom, WT[0], k_b, nullptr, kbuf, n, 0);
    gemm_f2<<<gblocks, 256>>>(atom, WT[1], q_b, nullptr, qbuf, n, 0);

    node_aggregate<<<n, 128>>>(bond, dd, attn);

    gemm_f2<<<gblocks, 256>>>(ftbuf, WT[2], l1b, nullptr, kbuf, n, 1);   // t1
    gemm_f2<<<gblocks, 256>>>(kbuf, WT[3], l2b, atom, qbuf, n, 0);       // he
    gemm_f2<<<gblocks, 256>>>(qbuf, WT[4], r1ab, nullptr, kbuf, n, 1);   // u1
    gemm_f2<<<gblocks, 256>>>(kbuf, WT[5], r1bb, qbuf, ftbuf, n, 1);     // he2
    gemm_f2<<<gblocks, 256>>>(ftbuf, WT[6], r2ab, nullptr, kbuf, n, 1);  // u3
    gemm_f2<<<gblocks, 256>>>(kbuf, WT[7], r2bb, ftbuf, out, n, 1);      // out
}

// round 7
// speedup vs baseline: 2.9114x; 1.3271x over previous
#include <cuda_runtime.h>
#include <cuda_bf16.h>
#include <cstdint>

#define NN   50000
#define EE   640000
#define HIDD 128

// ---------------- device scratch ----------------
__device__ float g_k[NN * HIDD];
__device__ float g_q[NN * HIDD];
__device__ float g_ft[NN * HIDD];
__device__ int   g_cnt[NN];
__device__ int   g_off[NN + 1];
__device__ int   g_cur[NN];
__device__ int   g_eid[EE];
__device__ int   g_esrc[EE];
__device__ int   g_bsum[256];
__device__ int   g_boff[256];

// ---------------- warp-mma helpers (sm_80-era PTX, valid on plain sm_103) ----------
__device__ __forceinline__ uint32_t smem_u32(const void* p)
{
    uint32_t a;
    asm("{ .reg .u64 t; cvta.to.shared.u64 t, %1; cvt.u32.u64 %0, t; }" : "=r"(a) : "l"(p));
    return a;
}
__device__ __forceinline__ void ldsm4(uint32_t& r0, uint32_t& r1, uint32_t& r2, uint32_t& r3,
                                      uint32_t addr)
{
    asm volatile("ldmatrix.sync.aligned.m8n8.x4.shared.b16 {%0,%1,%2,%3}, [%4];"
                 : "=r"(r0), "=r"(r1), "=r"(r2), "=r"(r3) : "r"(addr));
}
__device__ __forceinline__ void mma16816(float* c, const uint32_t* a, uint32_t b0, uint32_t b1)
{
    asm volatile(
        "mma.sync.aligned.m16n8k16.row.col.f32.bf16.bf16.f32 "
        "{%0,%1,%2,%3}, {%4,%5,%6,%7}, {%8,%9}, {%0,%1,%2,%3};"
        : "+f"(c[0]), "+f"(c[1]), "+f"(c[2]), "+f"(c[3])
        : "r"(a[0]), "r"(a[1]), "r"(a[2]), "r"(a[3]), "r"(b0), "r"(b1));
}

// smem tile layout: [128 rows][16 units of 16B], unit swizzle u ^= (r & 7)
__device__ __forceinline__ uint32_t sw(int r, int u) { return (uint32_t)(r * 256 + ((u ^ (r & 7)) << 4)); }

#define XH_OFF 0
#define XL_OFF 32768
#define WH_OFF 65536
#define WL_OFF 98304
#define SMEM_TOT 131072

// =============== bf16x3 tensor-core GEMM: Y = act(X @ W^T + b) [+ res] ===============
// grid: (ceil(n/128)), 256 threads. Full N=128, K=128 in one tile.
__global__ __launch_bounds__(256) void gemm_mma(
    const float* __restrict__ X, const float* __restrict__ W,
    const float* __restrict__ bias, const float* __restrict__ res,
    float* __restrict__ Y, int n, int doRelu)
{
    extern __shared__ char smem[];
    uint32_t sb = smem_u32(smem);
    int tid = threadIdx.x, wid = tid >> 5, lane = tid & 31;
    int row0 = blockIdx.x * 128;

    // ---- stage X (hi/lo) and W (hi/lo) into swizzled smem ----
    // 2048 units per tile, 8 per thread
#pragma unroll
    for (int j = 0; j < 8; j++) {
        int i = tid + 256 * j;
        int r = i >> 4, u = i & 15;
        int gr = row0 + r;
        float4 f0 = make_float4(0.f, 0.f, 0.f, 0.f), f1 = f0;
        if (gr < n) {
            f0 = ((const float4*)(X + (size_t)gr * HIDD))[u * 2];
            f1 = ((const float4*)(X + (size_t)gr * HIDD))[u * 2 + 1];
        }
        float f[8] = {f0.x, f0.y, f0.z, f0.w, f1.x, f1.y, f1.z, f1.w};
        __nv_bfloat162 hi[4], lo[4];
#pragma unroll
        for (int p = 0; p < 4; p++) {
            __nv_bfloat16 h0 = __float2bfloat16(f[p * 2]);
            __nv_bfloat16 h1 = __float2bfloat16(f[p * 2 + 1]);
            hi[p] = __nv_bfloat162(h0, h1);
            lo[p] = __nv_bfloat162(__float2bfloat16(f[p * 2] - __bfloat162float(h0)),
                                   __float2bfloat16(f[p * 2 + 1] - __bfloat162float(h1)));
        }
        uint32_t o = sw(r, u);
        *(uint4*)(smem + XH_OFF + o) = *(uint4*)hi;
        *(uint4*)(smem + XL_OFF + o) = *(uint4*)lo;
    }
#pragma unroll
    for (int j = 0; j < 8; j++) {
        int i = tid + 256 * j;
        int r = i >> 4, u = i & 15;
        float4 f0 = ((const float4*)(W + (size_t)r * HIDD))[u * 2];
        float4 f1 = ((const float4*)(W + (size_t)r * HIDD))[u * 2 + 1];
        float f[8] = {f0.x, f0.y, f0.z, f0.w, f1.x, f1.y, f1.z, f1.w};
        __nv_bfloat162 hi[4], lo[4];
#pragma unroll
        for (int p = 0; p < 4; p++) {
            __nv_bfloat16 h0 = __float2bfloat16(f[p * 2]);
            __nv_bfloat16 h1 = __float2bfloat16(f[p * 2 + 1]);
            hi[p] = __nv_bfloat162(h0, h1);
            lo[p] = __nv_bfloat162(__float2bfloat16(f[p * 2] - __bfloat162float(h0)),
                                   __float2bfloat16(f[p * 2 + 1] - __bfloat162float(h1)));
        }
        uint32_t o = sw(r, u);
        *(uint4*)(smem + WH_OFF + o) = *(uint4*)hi;
        *(uint4*)(smem + WL_OFF + o) = *(uint4*)lo;
    }
    __syncthreads();

    // ---- warp tiles: warp_m = wid>>1 (rows 32*), warp_n = wid&1 (cols 64*) ----
    int m0 = (wid >> 1) * 32;
    int n0 = (wid & 1) * 64;
    int sel = lane >> 3, lr = lane & 7;
    int us = sel >> 1;                 // unit offset within kstep
    int ra = (sel & 1) * 8 + lr;       // row offset within 16-row atom

    float acc[2][8][4];
#pragma unroll
    for (int i = 0; i < 2; i++)
#pragma unroll
        for (int a = 0; a < 8; a++)
#pragma unroll
            for (int p = 0; p < 4; p++) acc[i][a][p] = 0.f;

    // per-thread ldmatrix row indices
    int arow[2], brow[4];
#pragma unroll
    for (int i = 0; i < 2; i++) arow[i] = m0 + i * 16 + ra;
#pragma unroll
    for (int j = 0; j < 4; j++) brow[j] = n0 + j * 16 + ra;

#pragma unroll
    for (int k = 0; k < 8; k++) {
        int u = 2 * k + us;
        uint32_t ah[2][4], al[2][4], bb[4][4];
#pragma unroll
        for (int i = 0; i < 2; i++) {
            uint32_t o = sw(arow[i], u);
            ldsm4(ah[i][0], ah[i][1], ah[i][2], ah[i][3], sb + XH_OFF + o);
            ldsm4(al[i][0], al[i][1], al[i][2], al[i][3], sb + XL_OFF + o);
        }
#pragma unroll
        for (int j = 0; j < 4; j++) {
            uint32_t o = sw(brow[j], u);
            ldsm4(bb[j][0], bb[j][1], bb[j][2], bb[j][3], sb + WH_OFF + o);
        }
        // Xh*Wh + Xl*Wh
#pragma unroll
        for (int j = 0; j < 4; j++)
#pragma unroll
            for (int p = 0; p < 2; p++) {
                int a = 2 * j + p;
#pragma unroll
                for (int i = 0; i < 2; i++) {
                    mma16816(acc[i][a], ah[i], bb[j][p], bb[j][p + 2]);
                    mma16816(acc[i][a], al[i], bb[j][p], bb[j][p + 2]);
                }
            }
        // Xh*Wl
#pragma unroll
        for (int j = 0; j < 4; j++) {
            uint32_t o = sw(brow[j], u);
            ldsm4(bb[j][0], bb[j][1], bb[j][2], bb[j][3], sb + WL_OFF + o);
        }
#pragma unroll
        for (int j = 0; j < 4; j++)
#pragma unroll
            for (int p = 0; p < 2; p++) {
                int a = 2 * j + p;
#pragma unroll
                for (int i = 0; i < 2; i++)
                    mma16816(acc[i][a], ah[i], bb[j][p], bb[j][p + 2]);
            }
    }

    // ---- epilogue: direct stores, c-frag rows lane>>2 (+8), col pair 2*(lane&3) ----
#pragma unroll
    for (int i = 0; i < 2; i++) {
        int rbase = row0 + m0 + i * 16 + (lane >> 2);
#pragma unroll
        for (int a = 0; a < 8; a++) {
            int col = n0 + a * 8 + (lane & 3) * 2;
            float2 bv = *(const float2*)(bias + col);
#pragma unroll
            for (int h = 0; h < 2; h++) {
                int row = rbase + h * 8;
                if (row >= n) continue;
                float ox = acc[i][a][h * 2]     + bv.x;
                float oy = acc[i][a][h * 2 + 1] + bv.y;
                if (doRelu) { ox = fmaxf(ox, 0.f); oy = fmaxf(oy, 0.f); }
                if (res) {
                    float2 rv = *(const float2*)(res + (size_t)row * HIDD + col);
                    ox += rv.x; oy += rv.y;
                }
                *(float2*)(Y + (size_t)row * HIDD + col) = make_float2(ox, oy);
            }
        }
    }
}

// ---------------- CSR build ----------------
__global__ void zero_cnt(int n)
{
    int i = blockIdx.x * blockDim.x + threadIdx.x;
    if (i < n) g_cnt[i] = 0;
}

__global__ void count_deg(const int* __restrict__ dst, int E)
{
    int e = blockIdx.x * blockDim.x + threadIdx.x;
    if (e < E) atomicAdd(&g_cnt[dst[e]], 1);
}

__global__ __launch_bounds__(256) void scan_blk(int n)
{
    __shared__ int ws[8];
    int b = blockIdx.x, t = threadIdx.x;
    int idx = b * 256 + t;
    int lane = t & 31, wid = t >> 5;
    int v = (idx < n) ? g_cnt[idx] : 0;
    int incl = v;
#pragma unroll
    for (int o = 1; o < 32; o <<= 1) {
        int u = __shfl_up_sync(0xffffffffu, incl, o);
        if (lane >= o) incl += u;
    }
    if (lane == 31) ws[wid] = incl;
    __syncthreads();
    if (t < 8) {
        int a = ws[t];
        int p = a;
#pragma unroll
        for (int o = 1; o < 8; o <<= 1) {
            int u = __shfl_up_sync(0xffu, p, o);
            if (t >= o) p += u;
        }
        ws[t] = p - a;
        if (t == 7) g_bsum[b] = p;
    }
    __syncthreads();
    if (idx < n) g_off[idx] = incl - v + ws[wid];
}

__global__ __launch_bounds__(256) void scan_tot(int nb, int n)
{
    __shared__ int ws[8];
    int t = threadIdx.x;
    int lane = t & 31, wid = t >> 5;
    int v = (t < nb) ? g_bsum[t] : 0;
    int incl = v;
#pragma unroll
    for (int o = 1; o < 32; o <<= 1) {
        int u = __shfl_up_sync(0xffffffffu, incl, o);
        if (lane >= o) incl += u;
    }
    if (lane == 31) ws[wid] = incl;
    __syncthreads();
    if (t < 8) {
        int a = ws[t];
        int p = a;
#pragma unroll
        for (int o = 1; o < 8; o <<= 1) {
            int u = __shfl_up_sync(0xffu, p, o);
            if (t >= o) p += u;
        }
        ws[t] = p - a;
        if (t == 7) g_off[n] = p;
    }
    __syncthreads();
    g_boff[t] = incl - v + ws[wid];
}

__global__ void scan_add(int n)
{
    int b = blockIdx.x, t = threadIdx.x;
    int idx = b * 256 + t;
    if (idx < n) {
        int o = g_off[idx] + g_boff[b];
        g_off[idx] = o;
        g_cur[idx] = o;
    }
}

__global__ void bucket_edges(const int* __restrict__ src, const int* __restrict__ dst, int E)
{
    int e = blockIdx.x * blockDim.x + threadIdx.x;
    if (e >= E) return;
    int p = atomicAdd(&g_cur[dst[e]], 1);
    g_eid[p]  = e;
    g_esrc[p] = src[e];
}

// ---------------- fused per-node online-softmax aggregation (2-edge unrolled) -------
__global__ __launch_bounds__(128) void node_aggregate(
    const float* __restrict__ bond, const float* __restrict__ dd,
    const float* __restrict__ attn)
{
    int node = blockIdx.x;
    int t = threadIdx.x;
    int beg = g_off[node], end = g_off[node + 1];

    float qv = g_q[(size_t)node * HIDD + t];
    float av = attn[t];

    float m = __int_as_float(0xff800000);
    float s = 0.f, acc = 0.f;

    int i = beg;
    for (; i + 1 < end; i += 2) {
        int e0 = g_eid[i],     s0 = g_esrc[i];
        int e1 = g_eid[i + 1], s1 = g_esrc[i + 1];
        float kv0 = g_k[(size_t)s0 * HIDD + t];
        float kv1 = g_k[(size_t)s1 * HIDD + t];
        float bv0 = bond[(size_t)e0 * HIDD + t];
        float bv1 = bond[(size_t)e1 * HIDD + t];
        float dd0 = dd[e0];
        float dd1 = dd[e1];

        float v0 = kv0 + qv; v0 = (v0 > 0.f) ? v0 : 0.01f * v0;
        float v1 = kv1 + qv; v1 = (v1 > 0.f) ? v1 : 0.01f * v1;
        float p0 = v0 * av;
        float p1 = v1 * av;
#pragma unroll
        for (int o = 8; o; o >>= 1) {
            p0 += __shfl_xor_sync(0xffffffffu, p0, o, 16);
            p1 += __shfl_xor_sync(0xffffffffu, p1, o, 16);
        }
        float z0 = p0 + dd0;
        float z1 = p1 + dd1;
        float mn = fmaxf(m, fmaxf(z0, z1));
        float corr = __expf(m - mn);
        float w0 = __expf(z0 - mn);
        float w1 = __expf(z1 - mn);
        acc = acc * corr + w0 * bv0 + w1 * bv1;
        s   = s   * corr + w0 + w1;
        m   = mn;
    }
    if (i < end) {
        int e0 = g_eid[i], s0 = g_esrc[i];
        float kv0 = g_k[(size_t)s0 * HIDD + t];
        float bv0 = bond[(size_t)e0 * HIDD + t];
        float dd0 = dd[e0];
        float v0 = kv0 + qv; v0 = (v0 > 0.f) ? v0 : 0.01f * v0;
        float p0 = v0 * av;
#pragma unroll
        for (int o = 8; o; o >>= 1) p0 += __shfl_xor_sync(0xffffffffu, p0, o, 16);
        float z0 = p0 + dd0;
        float mn = fmaxf(m, z0);
        float corr = __expf(m - mn);
        float w0 = __expf(z0 - mn);
        acc = acc * corr + w0 * bv0;
        s   = s   * corr + w0;
    }
    g_ft[(size_t)node * HIDD + t] = (s > 0.f) ? acc / s : 0.f;
}

// ---------------- launch ----------------
extern "C" void kernel_launch(void* const* d_in, const int* in_sizes, int n_in,
                              void* d_out, int out_size)
{
    const int*   src  = (const int*)d_in[0];
    const int*   dst  = (const int*)d_in[1];
    const float* bond = (const float*)d_in[2];
    const float* atom = (const float*)d_in[3];
    const float* dd   = (const float*)d_in[4];
    const float* k_w  = (const float*)d_in[5];
    const float* k_b  = (const float*)d_in[6];
    const float* q_w  = (const float*)d_in[7];
    const float* q_b  = (const float*)d_in[8];
    const float* attn = (const float*)d_in[9];
    const float* l1w  = (const float*)d_in[10];
    const float* l1b  = (const float*)d_in[11];
    const float* l2w  = (const float*)d_in[12];
    const float* l2b  = (const float*)d_in[13];
    const float* r1aw = (const float*)d_in[14];
    const float* r1ab = (const float*)d_in[15];
    const float* r1bw = (const float*)d_in[16];
    const float* r1bb = (const float*)d_in[17];
    const float* r2aw = (const float*)d_in[18];
    const float* r2ab = (const float*)d_in[19];
    const float* r2bw = (const float*)d_in[20];
    const float* r2bb = (const float*)d_in[21];
    float* out = (float*)d_out;

    int E = in_sizes[0];
    int n = in_sizes[3] / HIDD;

    float *kbuf, *qbuf, *ftbuf;
    cudaGetSymbolAddress((void**)&kbuf,  g_k);
    cudaGetSymbolAddress((void**)&qbuf,  g_q);
    cudaGetSymbolAddress((void**)&ftbuf, g_ft);

    cudaFuncSetAttribute(gemm_mma, cudaFuncAttributeMaxDynamicSharedMemorySize, SMEM_TOT);

    int nb = (n + 255) / 256;

    zero_cnt<<<nb, 256>>>(n);
    count_deg<<<(E + 255) / 256, 256>>>(dst, E);
    scan_blk<<<nb, 256>>>(n);
    scan_tot<<<1, 256>>>(nb, n);
    scan_add<<<nb, 256>>>(n);
    bucket_edges<<<(E + 255) / 256, 256>>>(src, dst, E);

    int gblocks = (n + 127) / 128;
    gemm_mma<<<gblocks, 256, SMEM_TOT>>>(atom, k_w, k_b, nullptr, kbuf, n, 0);
    gemm_mma<<<gblocks, 256, SMEM_TOT>>>(atom, q_w, q_b, nullptr, qbuf, n, 0);

    node_aggregate<<<n, 128>>>(bond, dd, attn);

    gemm_mma<<<gblocks, 256, SMEM_TOT>>>(ftbuf, l1w, l1b, nullptr, kbuf, n, 1);   // t1
    gemm_mma<<<gblocks, 256, SMEM_TOT>>>(kbuf, l2w, l2b, atom, qbuf, n, 0);       // he
    gemm_mma<<<gblocks, 256, SMEM_TOT>>>(qbuf, r1aw, r1ab, nullptr, kbuf, n, 1);  // u1
    gemm_mma<<<gblocks, 256, SMEM_TOT>>>(kbuf, r1bw, r1bb, qbuf, ftbuf, n, 1);    // he2
    gemm_mma<<<gblocks, 256, SMEM_TOT>>>(ftbuf, r2aw, r2ab, nullptr, kbuf, n, 1); // u3
    gemm_mma<<<gblocks, 256, SMEM_TOT>>>(kbuf, r2bw, r2bb, ftbuf, out, n, 1);     // out
}

// round 8
// speedup vs baseline: 2.9808x; 1.0238x over previous
#include <cuda_runtime.h>
#include <cuda_bf16.h>
#include <cstdint>

#define NN   50000
#define EE   640000
#define HIDD 128

// ---------------- device scratch ----------------
__device__ float g_k[NN * HIDD];
__device__ float g_q[NN * HIDD];
__device__ float g_ft[NN * HIDD];
__device__ int   g_cnt[NN];
__device__ int   g_off[NN + 1];
__device__ int   g_cur[NN];
__device__ int   g_eid[EE];
__device__ int   g_esrc[EE];
__device__ int   g_bsum[256];
__device__ int   g_boff[256];

// ---------------- warp-mma helpers ----------------
__device__ __forceinline__ uint32_t smem_u32(const void* p)
{
    uint32_t a;
    asm("{ .reg .u64 t; cvta.to.shared.u64 t, %1; cvt.u32.u64 %0, t; }" : "=r"(a) : "l"(p));
    return a;
}
__device__ __forceinline__ void ldsm4(uint32_t& r0, uint32_t& r1, uint32_t& r2, uint32_t& r3,
                                      uint32_t addr)
{
    asm volatile("ldmatrix.sync.aligned.m8n8.x4.shared.b16 {%0,%1,%2,%3}, [%4];"
                 : "=r"(r0), "=r"(r1), "=r"(r2), "=r"(r3) : "r"(addr));
}
__device__ __forceinline__ void mma16816(float* c, const uint32_t* a, uint32_t b0, uint32_t b1)
{
    asm volatile(
        "mma.sync.aligned.m16n8k16.row.col.f32.bf16.bf16.f32 "
        "{%0,%1,%2,%3}, {%4,%5,%6,%7}, {%8,%9}, {%0,%1,%2,%3};"
        : "+f"(c[0]), "+f"(c[1]), "+f"(c[2]), "+f"(c[3])
        : "r"(a[0]), "r"(a[1]), "r"(a[2]), "r"(a[3]), "r"(b0), "r"(b1));
}

// smem tile layout: [128 rows][16 units of 16B], unit swizzle u ^= (r & 7)
__device__ __forceinline__ uint32_t sw(int r, int u)
{
    return (uint32_t)(r * 256 + ((u ^ (r & 7)) << 4));
}

#define XH_OFF  0
#define XL_OFF  32768
#define WH_OFF  65536
#define WL_OFF  98304
#define CAR_OFF 131072
#define SMEM_PROJ 131072
#define SMEM_MLP  196608

// split one fp32 float8 chunk into bf16 hi/lo pairs and write to swizzled smem
__device__ __forceinline__ void split_store(char* smem, int hi_off, int lo_off,
                                            int r, int u, const float* f)
{
    __nv_bfloat162 hi[4], lo[4];
#pragma unroll
    for (int p = 0; p < 4; p++) {
        __nv_bfloat16 h0 = __float2bfloat16(f[p * 2]);
        __nv_bfloat16 h1 = __float2bfloat16(f[p * 2 + 1]);
        hi[p] = __nv_bfloat162(h0, h1);
        lo[p] = __nv_bfloat162(__float2bfloat16(f[p * 2] - __bfloat162float(h0)),
                               __float2bfloat16(f[p * 2 + 1] - __bfloat162float(h1)));
    }
    uint32_t o = sw(r, u);
    *(uint4*)(smem + hi_off + o) = *(uint4*)hi;
    *(uint4*)(smem + lo_off + o) = *(uint4*)lo;
}

// stage a 128x128 fp32 matrix (rows row0..+127 of src, guard < n) into X hi/lo
__device__ __forceinline__ void stage_X(char* smem, const float* src, int row0, int n, int tid)
{
#pragma unroll
    for (int j = 0; j < 8; j++) {
        int i = tid + 256 * j;
        int r = i >> 4, u = i & 15;
        int gr = row0 + r;
        float4 f0 = make_float4(0.f, 0.f, 0.f, 0.f), f1 = f0;
        if (gr < n) {
            f0 = ((const float4*)(src + (size_t)gr * HIDD))[u * 2];
            f1 = ((const float4*)(src + (size_t)gr * HIDD))[u * 2 + 1];
        }
        float f[8] = {f0.x, f0.y, f0.z, f0.w, f1.x, f1.y, f1.z, f1.w};
        split_store(smem, XH_OFF, XL_OFF, r, u, f);
    }
}

// stage a 128x128 fp32 weight matrix into W hi/lo
__device__ __forceinline__ void stage_W(char* smem, const float* W, int tid)
{
#pragma unroll
    for (int j = 0; j < 8; j++) {
        int i = tid + 256 * j;
        int r = i >> 4, u = i & 15;
        float4 f0 = ((const float4*)(W + (size_t)r * HIDD))[u * 2];
        float4 f1 = ((const float4*)(W + (size_t)r * HIDD))[u * 2 + 1];
        float f[8] = {f0.x, f0.y, f0.z, f0.w, f1.x, f1.y, f1.z, f1.w};
        split_store(smem, WH_OFF, WL_OFF, r, u, f);
    }
}

// bf16x3 MMA over the staged tiles: acc[2][8][4] per thread (8 warps, 32x64 warp tile)
__device__ __forceinline__ void mma_tile(uint32_t sb, int wid, int lane, float acc[2][8][4])
{
    int m0 = (wid >> 1) * 32;
    int n0 = (wid & 1) * 64;
    int sel = lane >> 3, lr = lane & 7;
    int us = sel >> 1;
    int ra = (sel & 1) * 8 + lr;

#pragma unroll
    for (int i = 0; i < 2; i++)
#pragma unroll
        for (int a = 0; a < 8; a++)
#pragma unroll
            for (int p = 0; p < 4; p++) acc[i][a][p] = 0.f;

    int arow[2], brow[4];
#pragma unroll
    for (int i = 0; i < 2; i++) arow[i] = m0 + i * 16 + ra;
#pragma unroll
    for (int j = 0; j < 4; j++) brow[j] = n0 + j * 16 + ra;

#pragma unroll
    for (int k = 0; k < 8; k++) {
        int u = 2 * k + us;
        uint32_t ah[2][4], al[2][4], bb[4][4];
#pragma unroll
        for (int i = 0; i < 2; i++) {
            uint32_t o = sw(arow[i], u);
            ldsm4(ah[i][0], ah[i][1], ah[i][2], ah[i][3], sb + XH_OFF + o);
            ldsm4(al[i][0], al[i][1], al[i][2], al[i][3], sb + XL_OFF + o);
        }
#pragma unroll
        for (int j = 0; j < 4; j++) {
            uint32_t o = sw(brow[j], u);
            ldsm4(bb[j][0], bb[j][1], bb[j][2], bb[j][3], sb + WH_OFF + o);
        }
#pragma unroll
        for (int j = 0; j < 4; j++)
#pragma unroll
            for (int p = 0; p < 2; p++) {
                int a = 2 * j + p;
#pragma unroll
                for (int i = 0; i < 2; i++) {
                    mma16816(acc[i][a], ah[i], bb[j][p], bb[j][p + 2]);
                    mma16816(acc[i][a], al[i], bb[j][p], bb[j][p + 2]);
                }
            }
#pragma unroll
        for (int j = 0; j < 4; j++) {
            uint32_t o = sw(brow[j], u);
            ldsm4(bb[j][0], bb[j][1], bb[j][2], bb[j][3], sb + WL_OFF + o);
        }
#pragma unroll
        for (int j = 0; j < 4; j++)
#pragma unroll
            for (int p = 0; p < 2; p++) {
                int a = 2 * j + p;
#pragma unroll
                for (int i = 0; i < 2; i++)
                    mma16816(acc[i][a], ah[i], bb[j][p], bb[j][p + 2]);
            }
    }
}

// =============== fused k+q projection: one CTA = 128 rows, both GEMMs ===============
__global__ __launch_bounds__(256) void proj_kq(
    const float* __restrict__ atom,
    const float* __restrict__ k_w, const float* __restrict__ k_b,
    const float* __restrict__ q_w, const float* __restrict__ q_b,
    float* __restrict__ K, float* __restrict__ Q, int n)
{
    extern __shared__ char smem[];
    uint32_t sb = smem_u32(smem);
    int tid = threadIdx.x, wid = tid >> 5, lane = tid & 31;
    int row0 = blockIdx.x * 128;

    stage_X(smem, atom, row0, n, tid);

    float acc[2][8][4];
    int m0 = (wid >> 1) * 32;
    int n0 = (wid & 1) * 64;

#pragma unroll
    for (int t = 0; t < 2; t++) {
        const float* W = t ? q_w : k_w;
        const float* B = t ? q_b : k_b;
        float* Y = t ? Q : K;
        stage_W(smem, W, tid);
        __syncthreads();
        mma_tile(sb, wid, lane, acc);
#pragma unroll
        for (int i = 0; i < 2; i++) {
            int rbase = row0 + m0 + i * 16 + (lane >> 2);
#pragma unroll
            for (int a = 0; a < 8; a++) {
                int col = n0 + a * 8 + (lane & 3) * 2;
                float2 bv = *(const float2*)(B + col);
#pragma unroll
                for (int h = 0; h < 2; h++) {
                    int row = rbase + h * 8;
                    if (row >= n) continue;
                    *(float2*)(Y + (size_t)row * HIDD + col) =
                        make_float2(acc[i][a][h * 2] + bv.x, acc[i][a][h * 2 + 1] + bv.y);
                }
            }
        }
        __syncthreads();   // W reads (other warps) done before re-staging
    }
}

// =============== fused 6-layer MLP: ft -> out, all layers in one CTA ===============
__global__ __launch_bounds__(256) void mlp6(
    const float* __restrict__ FT, const float* __restrict__ atom,
    const float* __restrict__ l1w, const float* __restrict__ l1b,
    const float* __restrict__ l2w, const float* __restrict__ l2b,
    const float* __restrict__ r1aw, const float* __restrict__ r1ab,
    const float* __restrict__ r1bw, const float* __restrict__ r1bb,
    const float* __restrict__ r2aw, const float* __restrict__ r2ab,
    const float* __restrict__ r2bw, const float* __restrict__ r2bb,
    float* __restrict__ out, int n)
{
    extern __shared__ char smem[];
    uint32_t sb = smem_u32(smem);
    int tid = threadIdx.x, wid = tid >> 5, lane = tid & 31;
    int row0 = blockIdx.x * 128;

    const float* Ws[6] = {l1w, l2w, r1aw, r1bw, r2aw, r2bw};
    const float* Bs[6] = {l1b, l2b, r1ab, r1bb, r2ab, r2bb};
    // relu: 1,0,1,1,1,1 ; res: 0=none 1=atom 2=carry ; out: 0=X 1=X+carry 2=global
    const int reluF[6] = {1, 0, 1, 1, 1, 1};
    const int resF[6]  = {0, 1, 0, 2, 0, 2};
    const int outF[6]  = {0, 1, 0, 1, 0, 2};

    stage_X(smem, FT, row0, n, tid);

    float acc[2][8][4];
    int m0 = (wid >> 1) * 32;
    int n0 = (wid & 1) * 64;

#pragma unroll
    for (int L = 0; L < 6; L++) {
        stage_W(smem, Ws[L], tid);
        __syncthreads();                 // X + W staged, prior phase done
        mma_tile(sb, wid, lane, acc);

        // epilogue values into registers
        float vals[2][8][4];
#pragma unroll
        for (int i = 0; i < 2; i++) {
            int rbase = row0 + m0 + i * 16 + (lane >> 2);
#pragma unroll
            for (int a = 0; a < 8; a++) {
                int col = n0 + a * 8 + (lane & 3) * 2;
                float2 bv = *(const float2*)(Bs[L] + col);
#pragma unroll
                for (int h = 0; h < 2; h++) {
                    int row = rbase + h * 8;
                    float vx = acc[i][a][h * 2]     + bv.x;
                    float vy = acc[i][a][h * 2 + 1] + bv.y;
                    if (reluF[L]) { vx = fmaxf(vx, 0.f); vy = fmaxf(vy, 0.f); }
                    if (resF[L] == 1) {
                        float2 rv = make_float2(0.f, 0.f);
                        if (row < n) rv = *(const float2*)(atom + (size_t)row * HIDD + col);
                        vx += rv.x; vy += rv.y;
                    } else if (resF[L] == 2) {
                        int lr = row - row0;
                        float2 rv = *(float2*)(smem + CAR_OFF + (lr * HIDD + col) * 4);
                        vx += rv.x; vy += rv.y;
                    }
                    vals[i][a][h * 2]     = vx;
                    vals[i][a][h * 2 + 1] = vy;
                }
            }
        }
        __syncthreads();                 // all warps finished reading X/W/carry

        // write results
#pragma unroll
        for (int i = 0; i < 2; i++) {
            int rl = m0 + i * 16 + (lane >> 2);
#pragma unroll
            for (int a = 0; a < 8; a++) {
                int col = n0 + a * 8 + (lane & 3) * 2;
                int u = col >> 3;
#pragma unroll
                for (int h = 0; h < 2; h++) {
                    int lr = rl + h * 8;
                    float vx = vals[i][a][h * 2], vy = vals[i][a][h * 2 + 1];
                    if (outF[L] == 2) {
                        int row = row0 + lr;
                        if (row < n)
                            *(float2*)(out + (size_t)row * HIDD + col) = make_float2(vx, vy);
                    } else {
                        __nv_bfloat16 hx = __float2bfloat16(vx);
                        __nv_bfloat16 hy = __float2bfloat16(vy);
                        __nv_bfloat162 hi(hx, hy);
                        __nv_bfloat162 lo(__float2bfloat16(vx - __bfloat162float(hx)),
                                          __float2bfloat16(vy - __bfloat162float(hy)));
                        uint32_t o = sw(lr, u) + ((col & 7) << 1);
                        *(__nv_bfloat162*)(smem + XH_OFF + o) = hi;
                        *(__nv_bfloat162*)(smem + XL_OFF + o) = lo;
                        if (outF[L] == 1)
                            *(float2*)(smem + CAR_OFF + (lr * HIDD + col) * 4) =
                                make_float2(vx, vy);
                    }
                }
            }
        }
        __syncthreads();                 // new X visible before next stage_W/mma
    }
}

// ---------------- CSR build ----------------
__global__ void zero_cnt(int n)
{
    int i = blockIdx.x * blockDim.x + threadIdx.x;
    if (i < n) g_cnt[i] = 0;
}

__global__ void count_deg(const int* __restrict__ dst, int E)
{
    int e = blockIdx.x * blockDim.x + threadIdx.x;
    if (e < E) atomicAdd(&g_cnt[dst[e]], 1);
}

__global__ __launch_bounds__(256) void scan_blk(int n)
{
    __shared__ int ws[8];
    int b = blockIdx.x, t = threadIdx.x;
    int idx = b * 256 + t;
    int lane = t & 31, wid = t >> 5;
    int v = (idx < n) ? g_cnt[idx] : 0;
    int incl = v;
#pragma unroll
    for (int o = 1; o < 32; o <<= 1) {
        int u = __shfl_up_sync(0xffffffffu, incl, o);
        if (lane >= o) incl += u;
    }
    if (lane == 31) ws[wid] = incl;
    __syncthreads();
    if (t < 8) {
        int a = ws[t];
        int p = a;
#pragma unroll
        for (int o = 1; o < 8; o <<= 1) {
            int u = __shfl_up_sync(0xffu, p, o);
            if (t >= o) p += u;
        }
        ws[t] = p - a;
        if (t == 7) g_bsum[b] = p;
    }
    __syncthreads();
    if (idx < n) g_off[idx] = incl - v + ws[wid];
}

__global__ __launch_bounds__(256) void scan_tot(int nb, int n)
{
    __shared__ int ws[8];
    int t = threadIdx.x;
    int lane = t & 31, wid = t >> 5;
    int v = (t < nb) ? g_bsum[t] : 0;
    int incl = v;
#pragma unroll
    for (int o = 1; o < 32; o <<= 1) {
        int u = __shfl_up_sync(0xffffffffu, incl, o);
        if (lane >= o) incl += u;
    }
    if (lane == 31) ws[wid] = incl;
    __syncthreads();
    if (t < 8) {
        int a = ws[t];
        int p = a;
#pragma unroll
        for (int o = 1; o < 8; o <<= 1) {
            int u = __shfl_up_sync(0xffu, p, o);
            if (t >= o) p += u;
        }
        ws[t] = p - a;
        if (t == 7) g_off[n] = p;
    }
    __syncthreads();
    g_boff[t] = incl - v + ws[wid];
}

__global__ void scan_add(int n)
{
    int b = blockIdx.x, t = threadIdx.x;
    int idx = b * 256 + t;
    if (idx < n) {
        int o = g_off[idx] + g_boff[b];
        g_off[idx] = o;
        g_cur[idx] = o;
    }
}

__global__ void bucket_edges(const int* __restrict__ src, const int* __restrict__ dst, int E)
{
    int e = blockIdx.x * blockDim.x + threadIdx.x;
    if (e >= E) return;
    int p = atomicAdd(&g_cur[dst[e]], 1);
    g_eid[p]  = e;
    g_esrc[p] = src[e];
}

// ---------------- fused per-node online-softmax aggregation (2-edge unrolled) -------
__global__ __launch_bounds__(128) void node_aggregate(
    const float* __restrict__ bond, const float* __restrict__ dd,
    const float* __restrict__ attn)
{
    int node = blockIdx.x;
    int t = threadIdx.x;
    int beg = g_off[node], end = g_off[node + 1];

    float qv = g_q[(size_t)node * HIDD + t];
    float av = attn[t];

    float m = __int_as_float(0xff800000);
    float s = 0.f, acc = 0.f;

    int i = beg;
    for (; i + 1 < end; i += 2) {
        int e0 = g_eid[i],     s0 = g_esrc[i];
        int e1 = g_eid[i + 1], s1 = g_esrc[i + 1];
        float kv0 = g_k[(size_t)s0 * HIDD + t];
        float kv1 = g_k[(size_t)s1 * HIDD + t];
        float bv0 = bond[(size_t)e0 * HIDD + t];
        float bv1 = bond[(size_t)e1 * HIDD + t];
        float dd0 = dd[e0];
        float dd1 = dd[e1];

        float v0 = kv0 + qv; v0 = (v0 > 0.f) ? v0 : 0.01f * v0;
        float v1 = kv1 + qv; v1 = (v1 > 0.f) ? v1 : 0.01f * v1;
        float p0 = v0 * av;
        float p1 = v1 * av;
#pragma unroll
        for (int o = 8; o; o >>= 1) {
            p0 += __shfl_xor_sync(0xffffffffu, p0, o, 16);
            p1 += __shfl_xor_sync(0xffffffffu, p1, o, 16);
        }
        float z0 = p0 + dd0;
        float z1 = p1 + dd1;
        float mn = fmaxf(m, fmaxf(z0, z1));
        float corr = __expf(m - mn);
        float w0 = __expf(z0 - mn);
        float w1 = __expf(z1 - mn);
        acc = acc * corr + w0 * bv0 + w1 * bv1;
        s   = s   * corr + w0 + w1;
        m   = mn;
    }
    if (i < end) {
        int e0 = g_eid[i], s0 = g_esrc[i];
        float kv0 = g_k[(size_t)s0 * HIDD + t];
        float bv0 = bond[(size_t)e0 * HIDD + t];
        float dd0 = dd[e0];
        float v0 = kv0 + qv; v0 = (v0 > 0.f) ? v0 : 0.01f * v0;
        float p0 = v0 * av;
#pragma unroll
        for (int o = 8; o; o >>= 1) p0 += __shfl_xor_sync(0xffffffffu, p0, o, 16);
        float z0 = p0 + dd0;
        float mn = fmaxf(m, z0);
        float corr = __expf(m - mn);
        float w0 = __expf(z0 - mn);
        acc = acc * corr + w0 * bv0;
        s   = s   * corr + w0;
    }
    g_ft[(size_t)node * HIDD + t] = (s > 0.f) ? acc / s : 0.f;
}

// ---------------- launch ----------------
extern "C" void kernel_launch(void* const* d_in, const int* in_sizes, int n_in,
                              void* d_out, int out_size)
{
    const int*   src  = (const int*)d_in[0];
    const int*   dst  = (const int*)d_in[1];
    const float* bond = (const float*)d_in[2];
    const float* atom = (const float*)d_in[3];
    const float* dd   = (const float*)d_in[4];
    const float* k_w  = (const float*)d_in[5];
    const float* k_b  = (const float*)d_in[6];
    const float* q_w  = (const float*)d_in[7];
    const float* q_b  = (const float*)d_in[8];
    const float* attn = (const float*)d_in[9];
    const float* l1w  = (const float*)d_in[10];
    const float* l1b  = (const float*)d_in[11];
    const float* l2w  = (const float*)d_in[12];
    const float* l2b  = (const float*)d_in[13];
    const float* r1aw = (const float*)d_in[14];
    const float* r1ab = (const float*)d_in[15];
    const float* r1bw = (const float*)d_in[16];
    const float* r1bb = (const float*)d_in[17];
    const float* r2aw = (const float*)d_in[18];
    const float* r2ab = (const float*)d_in[19];
    const float* r2bw = (const float*)d_in[20];
    const float* r2bb = (const float*)d_in[21];
    float* out = (float*)d_out;

    int E = in_sizes[0];
    int n = in_sizes[3] / HIDD;

    float *kbuf, *qbuf, *ftbuf;
    cudaGetSymbolAddress((void**)&kbuf,  g_k);
    cudaGetSymbolAddress((void**)&qbuf,  g_q);
    cudaGetSymbolAddress((void**)&ftbuf, g_ft);

    cudaFuncSetAttribute(proj_kq, cudaFuncAttributeMaxDynamicSharedMemorySize, SMEM_PROJ);
    cudaFuncSetAttribute(mlp6, cudaFuncAttributeMaxDynamicSharedMemorySize, SMEM_MLP);

    int nb = (n + 255) / 256;

    zero_cnt<<<nb, 256>>>(n);
    count_deg<<<(E + 255) / 256, 256>>>(dst, E);
    scan_blk<<<nb, 256>>>(n);
    scan_tot<<<1, 256>>>(nb, n);
    scan_add<<<nb, 256>>>(n);
    bucket_edges<<<(E + 255) / 256, 256>>>(src, dst, E);

    int gblocks = (n + 127) / 128;
    proj_kq<<<gblocks, 256, SMEM_PROJ>>>(atom, k_w, k_b, q_w, q_b, kbuf, qbuf, n);

    node_aggregate<<<n, 128>>>(bond, dd, attn);

    mlp6<<<gblocks, 256, SMEM_MLP>>>(ftbuf, atom,
                                     l1w, l1b, l2w, l2b,
                                     r1aw, r1ab, r1bw, r1bb,
                                     r2aw, r2ab, r2bw, r2bb,
                                     out, n);
}